// round 1
// baseline (speedup 1.0000x reference)
#include <cuda_runtime.h>
#include <math.h>

// ---------------------------------------------------------------------------
// PoincareLinear: N=32768, IN=1024, OUT=1024 (fp32)
//   z_unit = w / max(||w||_col, eps)  -> fold into per-column scale
//   cx2    = c * sum(x^2) per row
//   num    = 2*rc*(x@w)*colscale*cosh(2*rc*b) - (1+cx2)*sinh(2*rc*b)
//   mlr    = 2*wg/rc * asinh(num / max(1-cx2, eps))
//   y      = sinh(rc*mlr)/rc
//   y     /= 1 + sqrt(1 + c*sum(y^2))
//   project onto ball (norm clip at (1-0.004)/sqrt(c))
// ---------------------------------------------------------------------------

#define MAX_OUT 4096
#define MAX_N   65536

__device__ float g_colscale[MAX_OUT];
__device__ float g_coshb[MAX_OUT];
__device__ float g_sinhb[MAX_OUT];
__device__ float g_cx2[MAX_N];

// --- per-output-column prep: colscale, cosh/sinh of 2*rc*bias -------------
__global__ void prep_kernel(const float* __restrict__ w,
                            const float* __restrict__ bias,
                            const float* __restrict__ c_ptr,
                            int IN, int OUT) {
    int o = blockIdx.x * blockDim.x + threadIdx.x;
    if (o >= OUT) return;
    float s = 0.f;
    for (int i = 0; i < IN; ++i) {          // coalesced across threads
        float v = w[(size_t)i * OUT + o];
        s = fmaf(v, v, s);
    }
    float nrm = sqrtf(s);
    g_colscale[o] = 1.0f / fmaxf(nrm, 1e-15f);
    float rc = sqrtf(c_ptr[0]);
    float d = 2.0f * rc * bias[o];
    g_coshb[o] = coshf(d);
    g_sinhb[o] = sinhf(d);
}

// --- block reduction helper ------------------------------------------------
__device__ __forceinline__ float block_reduce_sum(float v) {
    __shared__ float red[32];
    int lane = threadIdx.x & 31;
    int wid  = threadIdx.x >> 5;
    #pragma unroll
    for (int off = 16; off > 0; off >>= 1)
        v += __shfl_down_sync(0xffffffff, v, off);
    if (lane == 0) red[wid] = v;
    __syncthreads();
    int nw = (blockDim.x + 31) >> 5;
    v = (threadIdx.x < nw) ? red[threadIdx.x] : 0.f;
    if (wid == 0) {
        #pragma unroll
        for (int off = 16; off > 0; off >>= 1)
            v += __shfl_down_sync(0xffffffff, v, off);
    }
    return v;  // valid in thread 0
}

// --- per-row cx2 = c * sum(x^2) ---------------------------------------------
__global__ void cx2_kernel(const float* __restrict__ x,
                           const float* __restrict__ c_ptr, int IN) {
    int row = blockIdx.x;
    const float4* xr = (const float4*)(x + (size_t)row * IN);
    float s = 0.f;
    int n4 = IN >> 2;
    for (int i = threadIdx.x; i < n4; i += blockDim.x) {
        float4 v = xr[i];
        s = fmaf(v.x, v.x, s); s = fmaf(v.y, v.y, s);
        s = fmaf(v.z, v.z, s); s = fmaf(v.w, v.w, s);
    }
    float tot = block_reduce_sum(s);
    if (threadIdx.x == 0) g_cx2[row] = c_ptr[0] * tot;
}

// --- SGEMM 128x128x16, 8x8 per thread, fused Poincare epilogue --------------
__global__ __launch_bounds__(256, 2)
void gemm_epi_kernel(const float* __restrict__ X,
                     const float* __restrict__ W,
                     const float* __restrict__ wg,
                     const float* __restrict__ c_ptr,
                     float* __restrict__ out,
                     int N, int IN, int OUT) {
    __shared__ float As[16][128];
    __shared__ float Bs[16][128];

    const int tid  = threadIdx.x;
    const int brow = blockIdx.y * 128;
    const int bcol = blockIdx.x * 128;
    const int tx = tid & 15;        // 16 col-threads
    const int ty = tid >> 4;        // 16 row-threads

    float acc[8][8];
    #pragma unroll
    for (int i = 0; i < 8; ++i)
        #pragma unroll
        for (int j = 0; j < 8; ++j) acc[i][j] = 0.f;

    for (int kt = 0; kt < IN; kt += 16) {
        // load A tile (128 rows x 16 k) transposed into As[k][row]
        #pragma unroll
        for (int l = 0; l < 2; ++l) {
            int idx = tid + l * 256;            // 0..511
            int r  = idx >> 2;
            int c4 = (idx & 3) << 2;
            float4 v = *(const float4*)(X + (size_t)(brow + r) * IN + kt + c4);
            As[c4 + 0][r] = v.x;
            As[c4 + 1][r] = v.y;
            As[c4 + 2][r] = v.z;
            As[c4 + 3][r] = v.w;
        }
        // load B tile (16 k x 128 cols)
        #pragma unroll
        for (int l = 0; l < 2; ++l) {
            int idx = tid + l * 256;
            int r  = idx >> 5;
            int c4 = (idx & 31) << 2;
            *(float4*)(&Bs[r][c4]) =
                *(const float4*)(W + (size_t)(kt + r) * OUT + bcol + c4);
        }
        __syncthreads();

        #pragma unroll
        for (int k = 0; k < 16; ++k) {
            float4 a0 = *(const float4*)(&As[k][ty * 8]);
            float4 a1 = *(const float4*)(&As[k][ty * 8 + 4]);
            float4 b0 = *(const float4*)(&Bs[k][tx * 8]);
            float4 b1 = *(const float4*)(&Bs[k][tx * 8 + 4]);
            float a[8] = {a0.x, a0.y, a0.z, a0.w, a1.x, a1.y, a1.z, a1.w};
            float b[8] = {b0.x, b0.y, b0.z, b0.w, b1.x, b1.y, b1.z, b1.w};
            #pragma unroll
            for (int i = 0; i < 8; ++i)
                #pragma unroll
                for (int j = 0; j < 8; ++j)
                    acc[i][j] = fmaf(a[i], b[j], acc[i][j]);
        }
        __syncthreads();
    }

    // ---- fused epilogue ----
    const float cval  = c_ptr[0];
    const float rc    = sqrtf(cval);
    const float invrc = 1.0f / rc;

    float colsc[8], chb[8], shb[8], g2[8];
    #pragma unroll
    for (int j = 0; j < 8; ++j) {
        int o = bcol + tx * 8 + j;
        colsc[j] = g_colscale[o];
        chb[j]   = g_coshb[o];
        shb[j]   = g_sinhb[o];
        g2[j]    = 2.0f * wg[o] * invrc;
    }

    #pragma unroll
    for (int i = 0; i < 8; ++i) {
        int n = brow + ty * 8 + i;
        float cx2   = g_cx2[n];
        float invd  = 1.0f / fmaxf(1.0f - cx2, 1e-15f);
        float onep  = 1.0f + cx2;
        float y[8];
        #pragma unroll
        for (int j = 0; j < 8; ++j) {
            float num = 2.0f * rc * acc[i][j] * colsc[j] * chb[j] - onep * shb[j];
            float mlr = g2[j] * asinhf(num * invd);
            y[j] = sinhf(rc * mlr) * invrc;
        }
        float* orow = out + (size_t)n * OUT + bcol + tx * 8;
        *(float4*)(orow)     = make_float4(y[0], y[1], y[2], y[3]);
        *(float4*)(orow + 4) = make_float4(y[4], y[5], y[6], y[7]);
    }
}

// --- per-row gyro-half map + ball projection (in place) --------------------
__global__ void project_kernel(float* __restrict__ out,
                               const float* __restrict__ c_ptr, int OUT) {
    int row = blockIdx.x;
    float4* yr = (float4*)(out + (size_t)row * OUT);
    int n4 = OUT >> 2;

    float s = 0.f;
    for (int i = threadIdx.x; i < n4; i += blockDim.x) {
        float4 v = yr[i];
        s = fmaf(v.x, v.x, s); s = fmaf(v.y, v.y, s);
        s = fmaf(v.z, v.z, s); s = fmaf(v.w, v.w, s);
    }
    float tot = block_reduce_sum(s);
    __shared__ float sh_scale;
    if (threadIdx.x == 0) {
        float c = c_ptr[0];
        float denom = 1.0f + sqrtf(1.0f + c * tot);
        float scale = 1.0f / denom;
        float norm  = fmaxf(sqrtf(tot) * scale, 1e-15f);
        float kk = -c;
        float maxnorm = (1.0f - 0.004f) * rsqrtf(fmaxf(fabsf(kk), 1e-15f));
        if (!(kk < 0.f)) maxnorm = 1e15f;
        if (norm > maxnorm) scale *= maxnorm / norm;
        sh_scale = scale;
    }
    __syncthreads();
    float scale = sh_scale;
    for (int i = threadIdx.x; i < n4; i += blockDim.x) {
        float4 v = yr[i];
        v.x *= scale; v.y *= scale; v.z *= scale; v.w *= scale;
        yr[i] = v;
    }
}

// ---------------------------------------------------------------------------
extern "C" void kernel_launch(void* const* d_in, const int* in_sizes, int n_in,
                              void* d_out, int out_size) {
    const float* x    = (const float*)d_in[0];
    const float* w    = (const float*)d_in[1];
    const float* wg   = (const float*)d_in[2];
    const float* bias = (const float*)d_in[3];
    const float* c    = (const float*)d_in[4];
    float* out = (float*)d_out;

    int OUT = in_sizes[2];
    int IN  = in_sizes[1] / OUT;
    int N   = in_sizes[0] / IN;

    prep_kernel<<<(OUT + 255) / 256, 256>>>(w, bias, c, IN, OUT);
    cx2_kernel<<<N, 256>>>(x, c, IN);
    dim3 grid(OUT / 128, N / 128);
    gemm_epi_kernel<<<grid, 256>>>(x, w, wg, c, out, N, IN, OUT);
    project_kernel<<<N, 256>>>(out, c, OUT);
}

// round 4
// speedup vs baseline: 2.5911x; 2.5911x over previous
#include <cuda_runtime.h>
#include <cuda_bf16.h>
#include <math.h>
#include <stdint.h>

// ---------------------------------------------------------------------------
// PoincareLinear via tcgen05 bf16 split GEMM (sm_103a path) with SIMT fallback
// body for the non-'a' PTX compilation stage the harness also emits.
//   dot = x@z_unit computed as x_hi@w_hi + x_hi@w_lo + x_lo@w_hi  (K=3*1024)
//   colscale folded into w before bf16 split (tcgen05 path).
//   num = 2*rc*dot*cosh(2rc b) - (1+cx2)*sinh(2rc b)
//   y   = sinh(2*wg*asinh(num/max(1-cx2,eps)))/rc
//   then gyro-half map + ball projection.
// ---------------------------------------------------------------------------

#if defined(__CUDA_ARCH_FEAT_SM103_ALL) || defined(__CUDA_ARCH_FEAT_SM100_ALL) || \
    defined(__CUDA_ARCH_SPECIFIC__) || defined(__CUDA_ARCH_FAMILY_SPECIFIC__)
#define HAS_TCGEN05 1
#else
#define HAS_TCGEN05 0
#endif

#define N_MAX   32768
#define IN_MAX  1024
#define OUT_MAX 1024

__device__ __nv_bfloat16 g_xhi[(size_t)N_MAX * IN_MAX];
__device__ __nv_bfloat16 g_xlo[(size_t)N_MAX * IN_MAX];
__device__ __nv_bfloat16 g_whi[(size_t)OUT_MAX * IN_MAX];   // [out][in], colscale folded
__device__ __nv_bfloat16 g_wlo[(size_t)OUT_MAX * IN_MAX];
__device__ float g_colscale[OUT_MAX];
__device__ float g_coshb[OUT_MAX];
__device__ float g_sinhb[OUT_MAX];
__device__ float g_cx2[N_MAX];

// Plain host/device constexpr — NOT a __device__ symbol (the cudafe stub
// must not need to register it in non-tcgen05 compilation stages).
constexpr uint64_t kSmemDescBaseSW128 =
    (uint64_t(2) << 61) | (uint64_t(1) << 46) | (uint64_t(64) << 32) | (uint64_t(1) << 16);

// ---------------- generic helpers -------------------------------------------
__device__ __forceinline__ uint32_t smem_u32(const void* p) {
    uint32_t a;
    asm("{ .reg .u64 t; cvta.to.shared.u64 t, %1; cvt.u32.u64 %0, t; }"
        : "=r"(a) : "l"(p));
    return a;
}
#define SW128(off) ((off) ^ (((off) >> 3) & 0x70))

__device__ __forceinline__ float block_reduce_sum(float v) {
    __shared__ float red[32];
    int lane = threadIdx.x & 31, wid = threadIdx.x >> 5;
    #pragma unroll
    for (int o = 16; o > 0; o >>= 1) v += __shfl_down_sync(0xffffffff, v, o);
    if (lane == 0) red[wid] = v;
    __syncthreads();
    int nw = (blockDim.x + 31) >> 5;
    v = (threadIdx.x < nw) ? red[threadIdx.x] : 0.f;
    if (wid == 0)
        #pragma unroll
        for (int o = 16; o > 0; o >>= 1) v += __shfl_down_sync(0xffffffff, v, o);
    return v;
}

#if HAS_TCGEN05
// ---------------- tcgen05 / mbarrier PTX wrappers (sm_103a only) -------------
__device__ __forceinline__ uint32_t elect_one() {
    uint32_t p;
    asm volatile("{ .reg .pred p; elect.sync _|p, 0xFFFFFFFF; selp.b32 %0,1,0,p; }"
                 : "=r"(p));
    return p;
}
__device__ __forceinline__ uint64_t make_desc(uint32_t addr) {
    return kSmemDescBaseSW128 | ((uint64_t)(addr >> 4) & 0x3FFF);
}
__device__ __forceinline__ void mbar_init(uint32_t a, uint32_t cnt) {
    asm volatile("mbarrier.init.shared.b64 [%0], %1;" :: "r"(a), "r"(cnt) : "memory");
}
__device__ __forceinline__ void mbar_wait(uint32_t a, uint32_t parity) {
    uint32_t done;
    asm volatile("{ .reg .pred p; mbarrier.try_wait.parity.acquire.cta.shared::cta.b64 p, [%1], %2;"
                 " selp.b32 %0,1,0,p; }" : "=r"(done) : "r"(a), "r"(parity) : "memory");
    if (!done) {
        asm volatile("{ .reg .pred P1; WL%=:"
                     " mbarrier.try_wait.parity.acquire.cta.shared::cta.b64 P1, [%0], %1, 0x989680;"
                     " @P1 bra.uni WD%=; bra.uni WL%=; WD%=: }"
                     :: "r"(a), "r"(parity) : "memory");
    }
}
__device__ __forceinline__ void tc_alloc(uint32_t smem_dst, uint32_t ncols) {
    asm volatile("tcgen05.alloc.cta_group::1.sync.aligned.shared::cta.b32 [%0], %1;"
                 :: "r"(smem_dst), "r"(ncols) : "memory");
}
__device__ __forceinline__ void tc_dealloc(uint32_t tmem, uint32_t ncols) {
    asm volatile("tcgen05.dealloc.cta_group::1.sync.aligned.b32 %0, %1;" :: "r"(tmem), "r"(ncols));
}
__device__ __forceinline__ void tc_relinquish() {
    asm volatile("tcgen05.relinquish_alloc_permit.cta_group::1.sync.aligned;");
}
__device__ __forceinline__ void tc_commit(uint32_t mbar) {
    asm volatile("tcgen05.commit.cta_group::1.mbarrier::arrive::one.shared::cluster.b64 [%0];"
                 :: "r"(mbar) : "memory");
}
__device__ __forceinline__ void mma_f16_ss(uint32_t d, uint64_t ad, uint64_t bd,
                                           uint32_t idesc, bool acc) {
    uint32_t en = acc ? 1u : 0u;
    asm volatile("{ .reg .pred p; setp.ne.u32 p, %4, 0;"
                 " tcgen05.mma.cta_group::1.kind::f16 [%0], %1, %2, %3, {%5,%5,%5,%5}, p; }"
                 :: "r"(d), "l"(ad), "l"(bd), "r"(idesc), "r"(en), "r"(0u) : "memory");
}
#define TC_LD_X32(r, addr) \
    asm volatile("tcgen05.ld.sync.aligned.32x32b.x32.b32 " \
        "{%0,%1,%2,%3,%4,%5,%6,%7,%8,%9,%10,%11,%12,%13,%14,%15," \
        "%16,%17,%18,%19,%20,%21,%22,%23,%24,%25,%26,%27,%28,%29,%30,%31}, [%32];" \
        : "=r"((r)[0]),"=r"((r)[1]),"=r"((r)[2]),"=r"((r)[3]),"=r"((r)[4]),"=r"((r)[5]), \
          "=r"((r)[6]),"=r"((r)[7]),"=r"((r)[8]),"=r"((r)[9]),"=r"((r)[10]),"=r"((r)[11]), \
          "=r"((r)[12]),"=r"((r)[13]),"=r"((r)[14]),"=r"((r)[15]),"=r"((r)[16]),"=r"((r)[17]), \
          "=r"((r)[18]),"=r"((r)[19]),"=r"((r)[20]),"=r"((r)[21]),"=r"((r)[22]),"=r"((r)[23]), \
          "=r"((r)[24]),"=r"((r)[25]),"=r"((r)[26]),"=r"((r)[27]),"=r"((r)[28]),"=r"((r)[29]), \
          "=r"((r)[30]),"=r"((r)[31]) : "r"(addr))
#define TC_WAIT_LD()  asm volatile("tcgen05.wait::ld.sync.aligned;" ::: "memory")
#define TC_FENCE_AFTER()  asm volatile("tcgen05.fence::after_thread_sync;" ::: "memory")
#define TC_FENCE_BEFORE() asm volatile("tcgen05.fence::before_thread_sync;" ::: "memory")
#define FENCE_ASYNC_SHARED() asm volatile("fence.proxy.async.shared::cta;" ::: "memory")
#endif // HAS_TCGEN05

// ---------------- prep: colscale + cosh/sinh(2 rc b) -------------------------
__global__ void prep_kernel(const float* __restrict__ w, const float* __restrict__ bias,
                            const float* __restrict__ c_ptr, int IN, int OUT) {
    int o = blockIdx.x * blockDim.x + threadIdx.x;
    if (o >= OUT) return;
    float s = 0.f;
    for (int i = 0; i < IN; ++i) { float v = w[(size_t)i * OUT + o]; s = fmaf(v, v, s); }
    g_colscale[o] = 1.0f / fmaxf(sqrtf(s), 1e-15f);
    float rc = sqrtf(c_ptr[0]);
    float d = 2.0f * rc * bias[o];
    g_coshb[o] = coshf(d);
    g_sinhb[o] = sinhf(d);
}

// ---------------- transpose + scale + bf16 split of w ------------------------
__global__ void convert_w_kernel(const float* __restrict__ w, int IN, int OUT) {
    __shared__ float t[32][33];
    int n0 = blockIdx.x * 32, k0 = blockIdx.y * 32;
    int tx = threadIdx.x, ty = threadIdx.y;
    t[ty][tx] = w[(size_t)(k0 + ty) * OUT + n0 + tx];
    __syncthreads();
    int n = n0 + ty, k = k0 + tx;
    float v = t[tx][ty] * g_colscale[n];
    __nv_bfloat16 hi = __float2bfloat16(v);
    float r = v - __bfloat162float(hi);
    g_whi[(size_t)n * IN + k] = hi;
    g_wlo[(size_t)n * IN + k] = __float2bfloat16(r);
}

// ---------------- x -> bf16 hi/lo, fused cx2 ---------------------------------
__global__ void convert_x_kernel(const float* __restrict__ x,
                                 const float* __restrict__ c_ptr, int IN) {
    int row = blockIdx.x;
    const float4* xr = (const float4*)(x + (size_t)row * IN);
    int n4 = IN >> 2;
    float s = 0.f;
    for (int i = threadIdx.x; i < n4; i += blockDim.x) {
        float4 v = xr[i];
        s = fmaf(v.x, v.x, s); s = fmaf(v.y, v.y, s);
        s = fmaf(v.z, v.z, s); s = fmaf(v.w, v.w, s);
        __nv_bfloat16 h0 = __float2bfloat16(v.x), h1 = __float2bfloat16(v.y);
        __nv_bfloat16 h2 = __float2bfloat16(v.z), h3 = __float2bfloat16(v.w);
        __nv_bfloat16 l0 = __float2bfloat16(v.x - __bfloat162float(h0));
        __nv_bfloat16 l1 = __float2bfloat16(v.y - __bfloat162float(h1));
        __nv_bfloat16 l2 = __float2bfloat16(v.z - __bfloat162float(h2));
        __nv_bfloat16 l3 = __float2bfloat16(v.w - __bfloat162float(h3));
        uint2 hp, lp;
        hp.x = ((uint32_t)__bfloat16_as_ushort(h1) << 16) | __bfloat16_as_ushort(h0);
        hp.y = ((uint32_t)__bfloat16_as_ushort(h3) << 16) | __bfloat16_as_ushort(h2);
        lp.x = ((uint32_t)__bfloat16_as_ushort(l1) << 16) | __bfloat16_as_ushort(l0);
        lp.y = ((uint32_t)__bfloat16_as_ushort(l3) << 16) | __bfloat16_as_ushort(l2);
        *(uint2*)(g_xhi + (size_t)row * IN + i * 4) = hp;
        *(uint2*)(g_xlo + (size_t)row * IN + i * 4) = lp;
    }
    float tot = block_reduce_sum(s);
    if (threadIdx.x == 0) g_cx2[row] = c_ptr[0] * tot;
}

// ---------------- GEMM + fused Poincare epilogue -----------------------------
#define MT 128
#define NT 256
#define KC 64
#define IDESC ((1u<<4) | (1u<<7) | (1u<<10) | ((NT/8u)<<17) | ((MT/16u)<<24))

#define OFF_TMEM 0u
#define OFF_MB0  8u
#define OFF_MB1  16u
#define OFF_PAR  64u                        // 3 * NT floats = 3072 B
#define OFF_T    4096u
#define ASZ      (MT * 128u)                // 16 KB
#define BSZ      (NT * 128u)                // 32 KB
#define SMEM_BYTES (OFF_T + 2u * (ASZ + BSZ))   // 102400

__global__ __launch_bounds__(256, 1)
void gemm_tc_kernel(const float* __restrict__ X, const float* __restrict__ W,
                    const float* __restrict__ wgp, const float* __restrict__ c_ptr,
                    float* __restrict__ out, int Nrows, int IN, int OUT) {
#if HAS_TCGEN05
    extern __shared__ char smem[];
    const uint32_t sb = smem_u32(smem);
    const int tid = threadIdx.x;
    const int wid = tid >> 5, lane = tid & 31;
    const int brow = blockIdx.y * MT, bcol = blockIdx.x * NT;
    const int nchunk = (3 * IN) / KC;   // 48

    if (wid == 0) { tc_alloc(sb + OFF_TMEM, 256); tc_relinquish(); }
    if (tid == 0) { mbar_init(sb + OFF_MB0, 1); mbar_init(sb + OFF_MB1, 1); }
    float* chb = (float*)(smem + OFF_PAR);
    float* shb = chb + NT;
    float* g2s = shb + NT;
    if (tid < NT) {
        int o = bcol + tid;
        chb[tid] = g_coshb[o];
        shb[tid] = g_sinhb[o];
        g2s[tid] = 2.0f * wgp[o];
    }
    __syncthreads();
    uint32_t tmem;
    asm volatile("ld.shared.b32 %0, [%1];" : "=r"(tmem) : "r"(sb + OFF_TMEM));

    uint32_t p0 = 0, p1 = 0;
    for (int c = 0; c < nchunk; ++c) {
        const int buf = c & 1;
        if (c >= 2) {
            if (buf == 0) { mbar_wait(sb + OFF_MB0, p0); p0 ^= 1; }
            else          { mbar_wait(sb + OFF_MB1, p1); p1 ^= 1; }
        }
        const int seg = c >> 4;            // 0: hi*hi, 1: hi*lo, 2: lo*hi
        const int k0  = (c & 15) * KC;
        const __nv_bfloat16* srcA = (seg == 2) ? g_xlo : g_xhi;
        const __nv_bfloat16* srcB = (seg == 1) ? g_wlo : g_whi;
        const uint32_t Aoff = OFF_T + buf * (ASZ + BSZ);
        const uint32_t Boff = Aoff + ASZ;
        #pragma unroll
        for (int l = 0; l < 4; ++l) {
            int idx = tid + l * 256;
            int r = idx >> 3, j = idx & 7;
            uint4 v = *(const uint4*)(srcA + (size_t)(brow + r) * IN + k0 + j * 8);
            *(uint4*)(smem + Aoff + SW128((uint32_t)(r * 128 + j * 16))) = v;
        }
        #pragma unroll
        for (int l = 0; l < 8; ++l) {
            int idx = tid + l * 256;
            int r = idx >> 3, j = idx & 7;
            uint4 v = *(const uint4*)(srcB + (size_t)(bcol + r) * IN + k0 + j * 8);
            *(uint4*)(smem + Boff + SW128((uint32_t)(r * 128 + j * 16))) = v;
        }
        FENCE_ASYNC_SHARED();
        __syncthreads();
        if (wid == 0 && elect_one()) {
            uint64_t ad = make_desc(sb + Aoff);
            uint64_t bd = make_desc(sb + Boff);
            #pragma unroll
            for (int k = 0; k < 4; ++k)
                mma_f16_ss(tmem, ad + k * 2, bd + k * 2, IDESC, (c > 0) || (k > 0));
            tc_commit(buf ? (sb + OFF_MB1) : (sb + OFF_MB0));
        }
        __syncthreads();
    }
    mbar_wait(sb + OFF_MB0, p0);
    mbar_wait(sb + OFF_MB1, p1);
    TC_FENCE_AFTER();

    // epilogue: warps 0-3 -> subpartition rows, col-halves split by wid>>2
    const float rc = sqrtf(c_ptr[0]);
    const float invrc = 1.0f / rc;
    const int sub = wid & 3, wg8 = wid >> 2;
    const int row = brow + sub * 32 + lane;
    const float cx2 = g_cx2[row];
    const float invd = 1.0f / fmaxf(1.0f - cx2, 1e-15f);
    const float onep = 1.0f + cx2;
    const float two_rc = 2.0f * rc;

    #pragma unroll
    for (int half = 0; half < 2; ++half) {
        const int cb = wg8 * 64 + half * 128;
        uint32_t d[64];
        TC_LD_X32(d, tmem + cb);
        TC_LD_X32(d + 32, tmem + cb + 32);
        TC_WAIT_LD();
        float* orow = out + (size_t)row * OUT + bcol + cb;
        #pragma unroll
        for (int j = 0; j < 64; j += 4) {
            float yv[4];
            #pragma unroll
            for (int q = 0; q < 4; ++q) {
                int col = cb + j + q;
                float dot = __uint_as_float(d[j + q]);
                float num = fmaf(two_rc * dot, chb[col], -onep * shb[col]);
                float a = g2s[col] * asinhf(num * invd);
                yv[q] = sinhf(a) * invrc;
            }
            *(float4*)(orow + j) = make_float4(yv[0], yv[1], yv[2], yv[3]);
        }
    }
    TC_FENCE_BEFORE();
    __syncthreads();
    if (wid == 0) tc_dealloc(tmem, 256);

#else  // ------------- SIMT fallback (non-'a' PTX stage) ---------------------
    extern __shared__ char smem[];
    float (*As)[128] = (float(*)[128])(smem);
    float (*Bs)[128] = (float(*)[128])(smem + 16 * 128 * 4);

    const int tid = threadIdx.x;
    const int brow = blockIdx.y * MT;
    const int tx = tid & 15, ty = tid >> 4;
    const float cval = c_ptr[0];
    const float rc = sqrtf(cval);
    const float invrc = 1.0f / rc;

    for (int half = 0; half < 2; ++half) {
        const int bcol = blockIdx.x * NT + half * 128;
        float acc[8][8];
        #pragma unroll
        for (int i = 0; i < 8; ++i)
            #pragma unroll
            for (int j = 0; j < 8; ++j) acc[i][j] = 0.f;

        for (int kt = 0; kt < IN; kt += 16) {
            #pragma unroll
            for (int l = 0; l < 2; ++l) {
                int idx = tid + l * 256;
                int r = idx >> 2, c4 = (idx & 3) << 2;
                float4 v = *(const float4*)(X + (size_t)(brow + r) * IN + kt + c4);
                As[c4 + 0][r] = v.x; As[c4 + 1][r] = v.y;
                As[c4 + 2][r] = v.z; As[c4 + 3][r] = v.w;
            }
            #pragma unroll
            for (int l = 0; l < 2; ++l) {
                int idx = tid + l * 256;
                int r = idx >> 5, c4 = (idx & 31) << 2;
                *(float4*)(&Bs[r][c4]) =
                    *(const float4*)(W + (size_t)(kt + r) * OUT + bcol + c4);
            }
            __syncthreads();
            #pragma unroll
            for (int k = 0; k < 16; ++k) {
                float a[8], b[8];
                #pragma unroll
                for (int q = 0; q < 8; ++q) a[q] = As[k][ty * 8 + q];
                #pragma unroll
                for (int q = 0; q < 8; ++q) b[q] = Bs[k][tx * 8 + q];
                #pragma unroll
                for (int i = 0; i < 8; ++i)
                    #pragma unroll
                    for (int j = 0; j < 8; ++j)
                        acc[i][j] = fmaf(a[i], b[j], acc[i][j]);
            }
            __syncthreads();
        }
        float colsc[8], chbv[8], shbv[8], g2v[8];
        #pragma unroll
        for (int j = 0; j < 8; ++j) {
            int o = bcol + tx * 8 + j;
            colsc[j] = g_colscale[o];
            chbv[j] = g_coshb[o];
            shbv[j] = g_sinhb[o];
            g2v[j] = 2.0f * wgp[o];
        }
        #pragma unroll
        for (int i = 0; i < 8; ++i) {
            int n = brow + ty * 8 + i;
            float cx2 = g_cx2[n];
            float invd = 1.0f / fmaxf(1.0f - cx2, 1e-15f);
            float onep = 1.0f + cx2;
            float y[8];
            #pragma unroll
            for (int j = 0; j < 8; ++j) {
                float num = 2.0f * rc * acc[i][j] * colsc[j] * chbv[j] - onep * shbv[j];
                float a = g2v[j] * asinhf(num * invd);
                y[j] = sinhf(a) * invrc;
            }
            float* orow = out + (size_t)n * OUT + bcol + tx * 8;
            *(float4*)(orow)     = make_float4(y[0], y[1], y[2], y[3]);
            *(float4*)(orow + 4) = make_float4(y[4], y[5], y[6], y[7]);
        }
        __syncthreads();
    }
#endif
}

// ---------------- gyro-half map + ball projection ---------------------------
__global__ void project_kernel(float* __restrict__ out,
                               const float* __restrict__ c_ptr, int OUT) {
    int row = blockIdx.x;
    float4* yr = (float4*)(out + (size_t)row * OUT);
    int n4 = OUT >> 2;
    float s = 0.f;
    for (int i = threadIdx.x; i < n4; i += blockDim.x) {
        float4 v = yr[i];
        s = fmaf(v.x, v.x, s); s = fmaf(v.y, v.y, s);
        s = fmaf(v.z, v.z, s); s = fmaf(v.w, v.w, s);
    }
    float tot = block_reduce_sum(s);
    __shared__ float sh_scale;
    if (threadIdx.x == 0) {
        float c = c_ptr[0];
        float denom = 1.0f + sqrtf(1.0f + c * tot);
        float scale = 1.0f / denom;
        float norm = fmaxf(sqrtf(tot) * scale, 1e-15f);
        float kk = -c;
        float maxnorm = (1.0f - 0.004f) * rsqrtf(fmaxf(fabsf(kk), 1e-15f));
        if (!(kk < 0.f)) maxnorm = 1e15f;
        if (norm > maxnorm) scale *= maxnorm / norm;
        sh_scale = scale;
    }
    __syncthreads();
    float scale = sh_scale;
    for (int i = threadIdx.x; i < n4; i += blockDim.x) {
        float4 v = yr[i];
        v.x *= scale; v.y *= scale; v.z *= scale; v.w *= scale;
        yr[i] = v;
    }
}

// ---------------------------------------------------------------------------
extern "C" void kernel_launch(void* const* d_in, const int* in_sizes, int n_in,
                              void* d_out, int out_size) {
    const float* x    = (const float*)d_in[0];
    const float* w    = (const float*)d_in[1];
    const float* wg   = (const float*)d_in[2];
    const float* bias = (const float*)d_in[3];
    const float* c    = (const float*)d_in[4];
    float* out = (float*)d_out;

    int OUT = in_sizes[2];
    int IN  = in_sizes[1] / OUT;
    int N   = in_sizes[0] / IN;

    static int smem_set = 0;
    if (!smem_set) {
        cudaFuncSetAttribute(gemm_tc_kernel, cudaFuncAttributeMaxDynamicSharedMemorySize,
                             SMEM_BYTES);
        smem_set = 1;
    }

    prep_kernel<<<(OUT + 255) / 256, 256>>>(w, bias, c, IN, OUT);
    convert_w_kernel<<<dim3(OUT / 32, IN / 32), dim3(32, 32)>>>(w, IN, OUT);
    convert_x_kernel<<<N, 256>>>(x, c, IN);
    dim3 grid(OUT / NT, N / MT);
    gemm_tc_kernel<<<grid, 256, SMEM_BYTES>>>(x, w, wg, c, out, N, IN, OUT);
    project_kernel<<<N, 256>>>(out, c, OUT);
}